// round 7
// baseline (speedup 1.0000x reference)
#include <cuda_runtime.h>
#include <cstdint>

#define BATCH 4
#define SEQ   4096
#define EMBED 1024
#define HEAD  64
#define ROWS  (BATCH * SEQ)
#define KSPLIT 2
#define KRANGE (SEQ / KSPLIT)
#define NT     (KRANGE / 64)

#define LOG2E 1.4426950408889634f

__device__ float g_w [192 * EMBED];
__device__ float g_q [ROWS * HEAD];
__device__ float g_k [ROWS * HEAD];
__device__ float g_vt[BATCH * HEAD * SEQ];
__device__ float g_qn[ROWS];          // ||q_i|| (of rounded q)
__device__ int   g_kmax_i[BATCH];     // max_j ||k_j|| per batch, float-as-int
__device__ float g_opart[KSPLIT * ROWS * HEAD];
__device__ float g_ml  [KSPLIT * ROWS * 2];

// ---------------------------------------------------------------------------
__device__ __forceinline__ unsigned f2tf(float f) {
    unsigned u;
    asm("cvt.rna.tf32.f32 %0, %1;" : "=r"(u) : "f"(f));
    return u;
}
__device__ __forceinline__ float f2tff(float f) { return __uint_as_float(f2tf(f)); }

__device__ __forceinline__ void mma8(float* d, unsigned a0, unsigned a1,
                                     unsigned a2, unsigned a3,
                                     unsigned b0, unsigned b1) {
    asm("mma.sync.aligned.m16n8k8.row.col.f32.tf32.tf32.f32 "
        "{%0,%1,%2,%3},{%4,%5,%6,%7},{%8,%9},{%0,%1,%2,%3};"
        : "+f"(d[0]), "+f"(d[1]), "+f"(d[2]), "+f"(d[3])
        : "r"(a0), "r"(a1), "r"(a2), "r"(a3), "r"(b0), "r"(b1));
}

__device__ __forceinline__ void cp16(void* sptr, const void* gaddr) {
    uint32_t sa = (uint32_t)__cvta_generic_to_shared(sptr);
    asm volatile("cp.async.ca.shared.global [%0], [%1], 16;" ::"r"(sa), "l"(gaddr));
}
__device__ __forceinline__ void cp_commit() { asm volatile("cp.async.commit_group;"); }

// ===========================================================================
// Weight pre-round + kmax init
// ===========================================================================
__global__ void __launch_bounds__(256) wcvt_kernel(const float* __restrict__ Wq,
                                                   const float* __restrict__ Wk,
                                                   const float* __restrict__ Wv) {
    if (blockIdx.x == 0 && threadIdx.x < BATCH) g_kmax_i[threadIdx.x] = 0;
    int idx4 = blockIdx.x * 256 + threadIdx.x;
    int n  = idx4 >> 8;
    int e4 = idx4 & 255;
    const float* src = (n < 64) ? Wq : (n < 128) ? Wk : Wv;
    float4 v = *(const float4*)(src + (size_t)(n & 63) * EMBED + 4 * e4);
    v.x = f2tff(v.x); v.y = f2tff(v.y); v.z = f2tff(v.z); v.w = f2tff(v.w);
    *(float4*)(g_w + (size_t)n * EMBED + 4 * e4) = v;
}

// ===========================================================================
// Projection (tf32 mma): tile 64 rows x 192 cols, 256 threads.
// ===========================================================================
#define PKC   32
#define PSTR  40
#define XS_F  (64 * PSTR)
#define WS_F  (192 * PSTR)
#define PROJ_SMEM_F (2 * (XS_F + WS_F))
#define PROJ_SMEM_B (PROJ_SMEM_F * 4)

__global__ void __launch_bounds__(256, 2)
proj_kernel(const float* __restrict__ x) {
    extern __shared__ float sm[];
    const int t = threadIdx.x, lane = t & 31, wid = t >> 5;
    const int g = lane >> 2, tq = lane & 3;
    const int wm = wid & 1, wn = wid >> 1;
    const size_t row0 = (size_t)blockIdx.x * 64;

    float acc[2][6][4];
#pragma unroll
    for (int mt = 0; mt < 2; mt++)
#pragma unroll
        for (int nt = 0; nt < 6; nt++)
#pragma unroll
            for (int i = 0; i < 4; i++) acc[mt][nt][i] = 0.f;

    const int NC = EMBED / PKC;

    auto issue = [&](int c) {
        int buf = c & 1;
        int k0  = c * PKC;
        float* Xs = sm + buf * (XS_F + WS_F);
        float* Ws = Xs + XS_F;
#pragma unroll
        for (int j = 0; j < 2; j++) {
            int id = t + 256 * j;
            int r = id >> 3, q = id & 7;
            cp16(&Xs[r * PSTR + 4 * q], x + (row0 + r) * EMBED + k0 + 4 * q);
        }
#pragma unroll
        for (int j = 0; j < 6; j++) {
            int id = t + 256 * j;
            int n = id >> 3, q = id & 7;
            cp16(&Ws[n * PSTR + 4 * q], g_w + (size_t)n * EMBED + k0 + 4 * q);
        }
        cp_commit();
    };

    issue(0);
    for (int c = 0; c < NC; c++) {
        if (c + 1 < NC) {
            issue(c + 1);
            asm volatile("cp.async.wait_group 1;");
        } else {
            asm volatile("cp.async.wait_group 0;");
        }
        __syncthreads();
        const float* Xs = sm + (c & 1) * (XS_F + WS_F);
        const float* Ws = Xs + XS_F;
#pragma unroll
        for (int kk = 0; kk < 4; kk++) {
            unsigned a[2][4];
#pragma unroll
            for (int mt = 0; mt < 2; mt++) {
                int r = 32 * wm + 16 * mt + g;
                float2 lo = *(const float2*)&Xs[(r    ) * PSTR + 8 * kk + 2 * tq];
                float2 hi = *(const float2*)&Xs[(r + 8) * PSTR + 8 * kk + 2 * tq];
                a[mt][0] = f2tf(lo.x); a[mt][1] = f2tf(hi.x);
                a[mt][2] = f2tf(lo.y); a[mt][3] = f2tf(hi.y);
            }
#pragma unroll
            for (int nt = 0; nt < 6; nt++) {
                uint2 bb = *(const uint2*)&Ws[(48 * wn + 8 * nt + g) * PSTR + 8 * kk + 2 * tq];
#pragma unroll
                for (int mt = 0; mt < 2; mt++)
                    mma8(acc[mt][nt], a[mt][0], a[mt][1], a[mt][2], a[mt][3],
                         bb.x, bb.y);
            }
        }
        __syncthreads();
    }

#pragma unroll
    for (int mt = 0; mt < 2; mt++) {
#pragma unroll
        for (int nt = 0; nt < 6; nt++) {
            int c0 = 48 * wn + 8 * nt + 2 * tq;
            int msel = c0 >> 6;
            int h    = c0 & 63;
            int r1 = (int)row0 + 32 * wm + 16 * mt + g;
            int r2 = r1 + 8;
            float* a = acc[mt][nt];
            float a0 = f2tff(a[0]), a1 = f2tff(a[1]);
            float a2 = f2tff(a[2]), a3 = f2tff(a[3]);
            if (msel == 0) {
                *(float2*)&g_q[(size_t)r1 * 64 + h] = make_float2(a0, a1);
                *(float2*)&g_q[(size_t)r2 * 64 + h] = make_float2(a2, a3);
            } else if (msel == 1) {
                *(float2*)&g_k[(size_t)r1 * 64 + h] = make_float2(a0, a1);
                *(float2*)&g_k[(size_t)r2 * 64 + h] = make_float2(a2, a3);
            } else {
                int b1 = r1 >> 12, n1 = r1 & 4095;
                int b2 = r2 >> 12, n2 = r2 & 4095;
                g_vt[((size_t)b1 * 64 + h    ) * SEQ + n1] = a0;
                g_vt[((size_t)b1 * 64 + h + 1) * SEQ + n1] = a1;
                g_vt[((size_t)b2 * 64 + h    ) * SEQ + n2] = a2;
                g_vt[((size_t)b2 * 64 + h + 1) * SEQ + n2] = a3;
            }
        }
    }
}

// ===========================================================================
// Norms: g_qn[row] = ||q_row||, g_kmax_i[b] = max ||k_row|| (float-as-int)
// ===========================================================================
__global__ void __launch_bounds__(128) norm_kernel() {
    int row = blockIdx.x * 128 + threadIdx.x;
    float nq = 0.f, nk = 0.f;
#pragma unroll
    for (int i = 0; i < 16; i++) {
        float4 qv = *(const float4*)&g_q[(size_t)row * 64 + 4 * i];
        float4 kv = *(const float4*)&g_k[(size_t)row * 64 + 4 * i];
        nq += qv.x * qv.x + qv.y * qv.y + qv.z * qv.z + qv.w * qv.w;
        nk += kv.x * kv.x + kv.y * kv.y + kv.z * kv.z + kv.w * kv.w;
    }
    g_qn[row] = sqrtf(nq);
    float nkr = sqrtf(nk);
#pragma unroll
    for (int d = 16; d; d >>= 1)
        nkr = fmaxf(nkr, __shfl_xor_sync(0xffffffffu, nkr, d));
    if ((threadIdx.x & 31) == 0)
        atomicMax(&g_kmax_i[row >> 12], __float_as_int(nkr));
}

// ===========================================================================
// Flash attention, tf32 mma, STATIC max (Cauchy-Schwarz bound): no running
// max, no corrections, no per-tile reductions. Per 8-col chunk: 16 S-mmas ->
// elementwise exp2 -> 16 PV-mmas, fully fused. BQ=128, BK=64, 128 threads
// (4 warps x 32 rows), split-K x2, 2 CTAs/SM.
// ===========================================================================
#define STR 72
#define S_Q  0                        // 128 x 72
#define S_K  9216                     // 2 x 64 x 72
#define S_V  18432                    // 2 x 64 x 72
#define S_M  27648                    // 2 x 64
#define ATTN_SMEM_F 27776
#define ATTN_SMEM_B (ATTN_SMEM_F * 4) // 111104 B

__global__ void __launch_bounds__(128, 2)
attn_kernel(const int* __restrict__ mask) {
    extern __shared__ float sm[];
    float* Qs = sm + S_Q;
    float* Kb = sm + S_K;
    float* Vb = sm + S_V;
    float* Mb = sm + S_M;

    const int t = threadIdx.x, lane = t & 31;
    const int g = lane >> 2, tq = lane & 3;
    const int r0 = (t >> 5) * 32;
    const int b  = blockIdx.y, z = blockIdx.z;
    const int q0 = blockIdx.x * 128;
    const int koff = z * KRANGE;

    const float* qbase = g_q + ((size_t)b * SEQ + q0) * HEAD;
    const float* kbase = g_k + ((size_t)b * SEQ + koff) * HEAD;
    const float* vbase = g_vt + (size_t)b * HEAD * SEQ + koff;

    // ---- stage Q ----
#pragma unroll
    for (int j = 0; j < 16; j++) {
        int id = t + 128 * j;
        int r = id >> 4, q = id & 15;
        cp16(&Qs[r * STR + 4 * q], qbase + (size_t)r * 64 + 4 * q);
    }
    cp_commit();

    auto issue = [&](int it) {
        int bf = it & 1;
        float* Ks = Kb + bf * (64 * STR);
        float* Vs = Vb + bf * (64 * STR);
#pragma unroll
        for (int j = 0; j < 8; j++) {
            int id = t + 128 * j;
            int r = id >> 4, q = id & 15;
            cp16(&Ks[r * STR + 4 * q], kbase + (size_t)(it * 64 + r) * 64 + 4 * q);
            cp16(&Vs[r * STR + 4 * q], vbase + (size_t)r * SEQ + it * 64 + 4 * q);
        }
        if (t < 64)
            Mb[bf * 64 + t] = (mask[b * SEQ + koff + it * 64 + t] == 0) ? 0.f : 1.f;
        cp_commit();
    };

    issue(0);

    // ---- static row bounds: M_i = ||q_i|| * kmax_b * SC2 (log2 domain) ----
    const float SC2 = 0.125f * LOG2E;
    const float kmax = __int_as_float(g_kmax_i[b]);
    float negM[2][2];
#pragma unroll
    for (int rg = 0; rg < 2; rg++) {
        size_t rr = (size_t)b * SEQ + q0 + r0 + 16 * rg + g;
        negM[rg][0] = -g_qn[rr]     * kmax * SC2;
        negM[rg][1] = -g_qn[rr + 8] * kmax * SC2;
    }

    asm volatile("cp.async.wait_group 1;");   // Q group done
    __syncthreads();

    // ---- hoist Q fragments ----
    unsigned qa[2][8][4];
#pragma unroll
    for (int rg = 0; rg < 2; rg++)
#pragma unroll
        for (int kk = 0; kk < 8; kk++) {
            uint2 lo = *(const uint2*)&Qs[(r0 + 16 * rg + g    ) * STR + 8 * kk + 2 * tq];
            uint2 hi = *(const uint2*)&Qs[(r0 + 16 * rg + g + 8) * STR + 8 * kk + 2 * tq];
            qa[rg][kk][0] = lo.x; qa[rg][kk][1] = hi.x;
            qa[rg][kk][2] = lo.y; qa[rg][kk][3] = hi.y;
        }

    float l[2][2] = {{0.f, 0.f}, {0.f, 0.f}};
    float o[2][8][4];
#pragma unroll
    for (int rg = 0; rg < 2; rg++)
#pragma unroll
        for (int nt = 0; nt < 8; nt++)
#pragma unroll
            for (int i = 0; i < 4; i++) o[rg][nt][i] = 0.f;

    for (int it = 0; it < NT; it++) {
        if (it + 1 < NT) {
            issue(it + 1);
            asm volatile("cp.async.wait_group 1;");
        } else {
            asm volatile("cp.async.wait_group 0;");
        }
        __syncthreads();
        const int bf = it & 1;
        const float* Ks = Kb + bf * (64 * STR);
        const float* Vs = Vb + bf * (64 * STR);
        const float* mk = Mb + bf * 64;

#pragma unroll
        for (int nt = 0; nt < 8; nt++) {
            // ---- S chunk: rows 32 (2 rg), cols 8*nt..8*nt+7 ----
            float s0[4] = {0.f, 0.f, 0.f, 0.f};
            float s1[4] = {0.f, 0.f, 0.f, 0.f};
#pragma unroll
            for (int kk = 0; kk < 8; kk++) {
                uint2 bb = *(const uint2*)&Ks[(8 * nt + g) * STR + 8 * kk + 2 * tq];
                mma8(s0, qa[0][kk][0], qa[0][kk][1], qa[0][kk][2], qa[0][kk][3],
                     bb.x, bb.y);
                mma8(s1, qa[1][kk][0], qa[1][kk][1], qa[1][kk][2], qa[1][kk][3],
                     bb.x, bb.y);
            }
            // ---- static-max softmax, elementwise ----
            float2 mm = *(const float2*)&mk[8 * nt + 2 * tq];
            float p00 = exp2f(fmaf(s0[0], SC2, negM[0][0])) * mm.x;
            float p01 = exp2f(fmaf(s0[1], SC2, negM[0][0])) * mm.y;
            float p02 = exp2f(fmaf(s0[2], SC2, negM[0][1])) * mm.x;
            float p03 = exp2f(fmaf(s0[3], SC2, negM[0][1])) * mm.y;
            float p10 = exp2f(fmaf(s1[0], SC2, negM[1][0])) * mm.x;
            float p11 = exp2f(fmaf(s1[1], SC2, negM[1][0])) * mm.y;
            float p12 = exp2f(fmaf(s1[2], SC2, negM[1][1])) * mm.x;
            float p13 = exp2f(fmaf(s1[3], SC2, negM[1][1])) * mm.y;
            unsigned u00 = f2tf(p00), u01 = f2tf(p01), u02 = f2tf(p02), u03 = f2tf(p03);
            unsigned u10 = f2tf(p10), u11 = f2tf(p11), u12 = f2tf(p12), u13 = f2tf(p13);
            l[0][0] += __uint_as_float(u00) + __uint_as_float(u01);
            l[0][1] += __uint_as_float(u02) + __uint_as_float(u03);
            l[1][0] += __uint_as_float(u10) + __uint_as_float(u11);
            l[1][1] += __uint_as_float(u12) + __uint_as_float(u13);
            // ---- PV chunk: k-cols 8*nt..8*nt+7, all 64 head cols ----
#pragma unroll
            for (int nh = 0; nh < 8; nh++) {
                uint2 bb = *(const uint2*)&Vs[(8 * nh + g) * STR + 8 * nt + 2 * tq];
                mma8(o[0][nh], u00, u02, u01, u03, bb.x, bb.y);
                mma8(o[1][nh], u10, u12, u11, u13, bb.x, bb.y);
            }
        }
        __syncthreads();
    }

    // ---- epilogue: reduce l across tq, store unnormalized O + (M, l) ----
#pragma unroll
    for (int rg = 0; rg < 2; rg++)
#pragma unroll
        for (int h = 0; h < 2; h++) {
            l[rg][h] += __shfl_xor_sync(0xffffffffu, l[rg][h], 1);
            l[rg][h] += __shfl_xor_sync(0xffffffffu, l[rg][h], 2);
        }
#pragma unroll
    for (int rg = 0; rg < 2; rg++) {
        size_t rlo = (size_t)z * ROWS + (size_t)b * SEQ + q0 + r0 + 16 * rg + g;
        size_t rhi = rlo + 8;
#pragma unroll
        for (int nt = 0; nt < 8; nt++) {
            int c0 = 8 * nt + 2 * tq;
            *(float2*)&g_opart[rlo * 64 + c0] = make_float2(o[rg][nt][0], o[rg][nt][1]);
            *(float2*)&g_opart[rhi * 64 + c0] = make_float2(o[rg][nt][2], o[rg][nt][3]);
        }
        if (tq == 0) {
            g_ml[rlo * 2] = -negM[rg][0]; g_ml[rlo * 2 + 1] = l[rg][0];
            g_ml[rhi * 2] = -negM[rg][1]; g_ml[rhi * 2 + 1] = l[rg][1];
        }
    }
}

// ===========================================================================
// Split-K combine (m values are log2-domain bounds; identical across splits)
// ===========================================================================
__global__ void __launch_bounds__(256) combine_kernel(float* __restrict__ out) {
    int t = threadIdx.x;
    int row = blockIdx.x * 16 + (t >> 4);
    int c   = (t & 15) * 4;
    float m0 = g_ml[(size_t)row * 2], l0 = g_ml[(size_t)row * 2 + 1];
    float m1 = g_ml[((size_t)ROWS + row) * 2], l1 = g_ml[((size_t)ROWS + row) * 2 + 1];
    float mx = fmaxf(m0, m1);
    float w0 = exp2f(m0 - mx), w1 = exp2f(m1 - mx);
    float inv = 1.f / (w0 * l0 + w1 * l1);
    w0 *= inv; w1 *= inv;
    float4 a = *(const float4*)&g_opart[(size_t)row * 64 + c];
    float4 d = *(const float4*)&g_opart[((size_t)ROWS + row) * 64 + c];
    float4 r = make_float4(w0 * a.x + w1 * d.x, w0 * a.y + w1 * d.y,
                           w0 * a.z + w1 * d.z, w0 * a.w + w1 * d.w);
    *(float4*)&out[(size_t)row * 64 + c] = r;
}

// ---------------------------------------------------------------------------
extern "C" void kernel_launch(void* const* d_in, const int* in_sizes, int n_in,
                              void* d_out, int out_size) {
    const float* x    = (const float*)d_in[0];
    const float* Wq   = (const float*)d_in[1];
    const float* Wk   = (const float*)d_in[2];
    const float* Wv   = (const float*)d_in[3];
    const int*   mask = (const int*)d_in[4];
    float*       out  = (float*)d_out;

    cudaFuncSetAttribute(proj_kernel, cudaFuncAttributeMaxDynamicSharedMemorySize,
                         PROJ_SMEM_B);
    cudaFuncSetAttribute(attn_kernel, cudaFuncAttributeMaxDynamicSharedMemorySize,
                         ATTN_SMEM_B);

    wcvt_kernel<<<192, 256>>>(Wq, Wk, Wv);
    proj_kernel<<<ROWS / 64, 256, PROJ_SMEM_B>>>(x);
    norm_kernel<<<ROWS / 128, 128>>>();
    attn_kernel<<<dim3(SEQ / 128, BATCH, KSPLIT), 128, ATTN_SMEM_B>>>(mask);
    combine_kernel<<<ROWS / 16, 256>>>(out);
}